// round 15
// baseline (speedup 1.0000x reference)
#include <cuda_runtime.h>
#include <cuda_bf16.h>
#include <math.h>

#define TT   196          // tokens
#define CC   640          // channels
#define KCH  64           // channels per K-chunk
#define NCH  (CC / KCH)   // 10
#define TPB  512
#define MTI  13           // m-tiles (208 rows padded)
#define NTI  25           // n-tiles (200 cols padded)
#define TILES (MTI * NTI) // 325
#define NWARP 16
#define MAXTPW 21         // max tiles per warp
#define ROWB 432          // tile row bytes (64ch rows x 216 tok x 2B), conflict-free stride
#define TILE_B (KCH * ROWB)   // 27648
#define DYN_SMEM (2 * TILE_B) // 55296
#define MAXB 512

__device__ float g_mult[MAXB * 2 * TT];

__device__ __forceinline__ unsigned su32(const void* p) {
    unsigned a;
    asm("{ .reg .u64 t; cvta.to.shared.u64 t, %1; cvt.u32.u64 %0, t; }"
        : "=r"(a) : "l"(p));
    return a;
}
__device__ __forceinline__ float warp_sum(float v) {
#pragma unroll
    for (int o = 16; o; o >>= 1) v += __shfl_xor_sync(0xffffffffu, v, o);
    return v;
}
__device__ __forceinline__ float warp_max(float v) {
#pragma unroll
    for (int o = 16; o; o >>= 1) v = fmaxf(v, __shfl_xor_sync(0xffffffffu, v, o));
    return v;
}

struct State {
    float ss[2 * TT];                 // sumsq (class, query)
    float invnc[208], invnq[208];     // 1/||token||, pad = 0
    float rW2[208], cW2[208];         // pass-2 weights (invnc*kq, invnq*kc), pad 0
    float rowacc[208], colacc[208];   // reduction outputs
    float mc[TT], mq[TT];             // means, then logits, then attn
    float h[64];                      // MLP hidden (class 0-31, query 32-63)
    float red[4];
};

__global__ void __launch_bounds__(TPB, 1)
corr_mma_kernel(const float* __restrict__ cls_all, const float* __restrict__ qry_all,
                const float* __restrict__ cw1, const float* __restrict__ cb1,
                const float* __restrict__ cw2, const float* __restrict__ cb2,
                const float* __restrict__ qw1, const float* __restrict__ qb1,
                const float* __restrict__ qw2, const float* __restrict__ qb2) {
    extern __shared__ char dynsmem[];
    __shared__ State s;

    const int tid  = threadIdx.x;
    const int lane = tid & 31;
    const int wid  = tid >> 5;       // 0..15
    const int b    = blockIdx.x;

    char* tA = dynsmem;              // class tile  [64 ch][216 tok] bf16
    char* tB = dynsmem + TILE_B;     // query tile
    const unsigned tA_sh = su32(tA);
    const unsigned tB_sh = su32(tB);

    const float* Xc = cls_all + (size_t)b * CC * TT;
    const float* Xq = qry_all + (size_t)b * CC * TT;

    // ---- preamble: zero sumsq accumulators and tile pad (tokens 196-215) ----
    for (int i = tid; i < 2 * TT; i += TPB) s.ss[i] = 0.f;
    if (tid < 128) {
        char* base = ((tid < 64) ? tA : tB) + (tid & 63) * ROWB + TT * 2;
#pragma unroll
        for (int jj = 0; jj < 10; ++jj)
            *reinterpret_cast<unsigned*>(base + jj * 4) = 0u;   // 40B = tokens 196-215
    }
    __syncthreads();

    // ---- per-warp tile range & register accumulators ------------------------
    const int tstart = (TILES * wid) / NWARP;
    const int tcnt   = (TILES * (wid + 1)) / NWARP - tstart;    // 20 or 21
    float acc[MAXTPW * 4];
#pragma unroll
    for (int i = 0; i < MAXTPW * 4; ++i) acc[i] = 0.f;

    // ---- K loop: stage chunk (fp32->bf16), sumsq scan, HMMA -----------------
#pragma unroll 1
    for (int k = 0; k < NCH; ++k) {
        const float* Pc = Xc + (size_t)k * KCH * TT;
        const float* Pq = Xq + (size_t)k * KCH * TT;
        // stage: [ch][tok] bf16; lanes cover consecutive token-quads -> LDG.128/STS.64
        for (int i = tid; i < 2 * KCH * 49; i += TPB) {
            const int side = i >= KCH * 49;
            const int j = side ? i - KCH * 49 : i;
            const int ch = j / 49;
            const int q  = j - ch * 49;
            const float4 v = *reinterpret_cast<const float4*>(
                (side ? Pq : Pc) + ch * TT + 4 * q);
            __nv_bfloat162 lo = __floats2bfloat162_rn(v.x, v.y);
            __nv_bfloat162 hi = __floats2bfloat162_rn(v.z, v.w);
            uint2 u;
            u.x = *reinterpret_cast<unsigned*>(&lo);
            u.y = *reinterpret_cast<unsigned*>(&hi);
            *reinterpret_cast<uint2*>((side ? tB : tA) + ch * ROWB + q * 8) = u;
        }
        __syncthreads();

        // sumsq scan: thread owns a token pair of one side
        if (tid < 2 * 98) {
            const int side = tid >= 98;
            const int p = tid - side * 98;
            const char* base = side ? tB : tA;
            float s0 = 0.f, s1 = 0.f;
#pragma unroll
            for (int ch = 0; ch < KCH; ++ch) {
                const unsigned u = *reinterpret_cast<const unsigned*>(base + ch * ROWB + p * 4);
                const float2 x = __bfloat1622float2(*reinterpret_cast<const __nv_bfloat162*>(&u));
                s0 = fmaf(x.x, x.x, s0);
                s1 = fmaf(x.y, x.y, s1);
            }
            s.ss[side * TT + 2 * p]     += s0;
            s.ss[side * TT + 2 * p + 1] += s1;
        }

        // HMMA: 4 k16-steps over this chunk
#pragma unroll 1
        for (int ks = 0; ks < 4; ++ks) {
            // lane-dependent ldmatrix offsets (trans: addrs index k-rows)
            const unsigned aofs = (unsigned)(ks * 16 + (lane & 7) + ((lane & 16) ? 8 : 0)) * ROWB
                                + ((lane & 8) ? 16u : 0u);
            const unsigned bofs = (unsigned)(ks * 16 + (lane & 7) + ((lane & 8) ? 8 : 0)) * ROWB;
            unsigned a0, a1, a2, a3;
            int prev_m = -1;
#pragma unroll
            for (int t = 0; t < MAXTPW; ++t) {
                if (t >= tcnt) break;
                const int ti = tstart + t;
                const int mm = ti / NTI;
                const int nn = ti - mm * NTI;
                if (mm != prev_m) {
                    asm volatile(
                        "ldmatrix.sync.aligned.m8n8.x4.trans.shared.b16 {%0,%1,%2,%3}, [%4];"
                        : "=r"(a0), "=r"(a1), "=r"(a2), "=r"(a3)
                        : "r"(tA_sh + aofs + (unsigned)mm * 32u));
                    prev_m = mm;
                }
                unsigned b0, b1;
                asm volatile(
                    "ldmatrix.sync.aligned.m8n8.x2.trans.shared.b16 {%0,%1}, [%2];"
                    : "=r"(b0), "=r"(b1)
                    : "r"(tB_sh + bofs + (unsigned)nn * 16u));
                asm volatile(
                    "mma.sync.aligned.m16n8k16.row.col.f32.bf16.bf16.f32 "
                    "{%0,%1,%2,%3}, {%4,%5,%6,%7}, {%8,%9}, {%0,%1,%2,%3};"
                    : "+f"(acc[4 * t]), "+f"(acc[4 * t + 1]),
                      "+f"(acc[4 * t + 2]), "+f"(acc[4 * t + 3])
                    : "r"(a0), "r"(a1), "r"(a2), "r"(a3), "r"(b0), "r"(b1));
            }
        }
        __syncthreads();   // tiles consumed; safe to overwrite next chunk
    }

    // ---- invn ----------------------------------------------------------------
    if (tid < TT) {
        s.invnc[tid] = 1.f / fmaxf(sqrtf(s.ss[tid]), 1e-12f);
        s.invnq[tid] = 1.f / fmaxf(sqrtf(s.ss[TT + tid]), 1e-12f);
    } else if (tid < 208) {
        s.invnc[tid] = 0.f;
        s.invnq[tid] = 0.f;
    }
    __syncthreads();

    // ---- dual weighted reduction over register corr (lambda, fully inlined) --
    auto reduce_pass = [&](const float* rowW, const float* colW) {
        if (tid < 208) { s.rowacc[tid] = 0.f; s.colacc[tid] = 0.f; }
        __syncthreads();
#pragma unroll
        for (int t = 0; t < MAXTPW; ++t) {
            if (t >= tcnt) break;
            const int ti = tstart + t;
            const int mm = ti / NTI;
            const int nn = ti - mm * NTI;
            const int gm = mm * 16 + (lane >> 2);
            const int gn = nn * 8 + 2 * (lane & 3);
            const float wr0 = rowW[gm], wr1 = rowW[gm + 8];
            const float wc0 = colW[gn], wc1 = colW[gn + 1];
            const float c0 = acc[4 * t], c1 = acc[4 * t + 1];
            const float c2 = acc[4 * t + 2], c3 = acc[4 * t + 3];
            float rs0 = c0 * wc0 + c1 * wc1;       // row gm
            float rs1 = c2 * wc0 + c3 * wc1;       // row gm+8
            float cs0 = c0 * wr0 + c2 * wr1;       // col gn
            float cs1 = c1 * wr0 + c3 * wr1;       // col gn+1
            rs0 += __shfl_xor_sync(0xffffffffu, rs0, 1);
            rs0 += __shfl_xor_sync(0xffffffffu, rs0, 2);
            rs1 += __shfl_xor_sync(0xffffffffu, rs1, 1);
            rs1 += __shfl_xor_sync(0xffffffffu, rs1, 2);
            cs0 += __shfl_xor_sync(0xffffffffu, cs0, 4);
            cs0 += __shfl_xor_sync(0xffffffffu, cs0, 8);
            cs0 += __shfl_xor_sync(0xffffffffu, cs0, 16);
            cs1 += __shfl_xor_sync(0xffffffffu, cs1, 4);
            cs1 += __shfl_xor_sync(0xffffffffu, cs1, 8);
            cs1 += __shfl_xor_sync(0xffffffffu, cs1, 16);
            if ((lane & 3) == 0) {
                atomicAdd(&s.rowacc[gm], rs0);
                atomicAdd(&s.rowacc[gm + 8], rs1);
            }
            if ((lane >> 2) == 0) {
                atomicAdd(&s.colacc[gn], cs0);
                atomicAdd(&s.colacc[gn + 1], cs1);
            }
        }
        __syncthreads();
    };

    // ---- Pass 1: means -------------------------------------------------------
    reduce_pass(s.invnc, s.invnq);
    if (tid < TT) {
        s.mq[tid] = s.rowacc[tid] * s.invnc[tid] * (1.f / (float)TT);  // row mean
        s.mc[tid] = s.colacc[tid] * s.invnq[tid] * (1.f / (float)TT);  // col mean
    }
    __syncthreads();

    // ---- MLPs: hidden (64 units x 8-way split-K), then k outputs -------------
    {
        const int u = tid >> 3;          // 0..63
        const int tg = tid & 7;
        const int side = u >= 32;        // 0=class(mc,cw), 1=query(mq,qw)
        const int hh = u & 31;
        const float* w1 = side ? qw1 : cw1;
        const float* b1 = side ? qb1 : cb1;
        const float* m  = side ? s.mq : s.mc;
        float a = 0.f;
        for (int t = tg; t < TT; t += 8)
            a = fmaf(m[t], w1[t * 32 + hh], a);
        a += __shfl_xor_sync(0xffffffffu, a, 1);
        a += __shfl_xor_sync(0xffffffffu, a, 2);
        a += __shfl_xor_sync(0xffffffffu, a, 4);
        if (tg == 0) s.h[u] = fmaxf(a + b1[hh], 0.f);
    }
    __syncthreads();
    if (tid < TT) {
        float kc = cb2[tid], kq = qb2[tid];
#pragma unroll
        for (int hh = 0; hh < 32; ++hh) {
            kc = fmaf(s.h[hh],      cw2[hh * TT + tid], kc);
            kq = fmaf(s.h[32 + hh], qw2[hh * TT + tid], kq);
        }
        s.cW2[tid] = s.invnq[tid] * kc;   // col weights for class logits
        s.rW2[tid] = s.invnc[tid] * kq;   // row weights for query logits
    } else if (tid < 208) {
        s.cW2[tid] = 0.f;
        s.rW2[tid] = 0.f;
    }
    __syncthreads();

    // ---- Pass 2: logits ------------------------------------------------------
    reduce_pass(s.rW2, s.cW2);
    if (tid < TT) {
        s.mc[tid] = s.rowacc[tid] * s.invnc[tid] * 40.f;  // class logits (/0.025)
        s.mq[tid] = s.colacc[tid] * s.invnq[tid] * 40.f;  // query logits
    }
    __syncthreads();

    // ---- softmax both sides, write multipliers -------------------------------
    if (wid == 0) {
        float v = -3.4e38f;
        for (int t = lane; t < TT; t += 32) v = fmaxf(v, s.mc[t]);
        v = warp_max(v);
        if (lane == 0) s.red[0] = v;
    }
    if (wid == 1) {
        float v = -3.4e38f;
        for (int t = lane; t < TT; t += 32) v = fmaxf(v, s.mq[t]);
        v = warp_max(v);
        if (lane == 0) s.red[1] = v;
    }
    __syncthreads();
    if (tid < TT) {
        s.mc[tid] = __expf(s.mc[tid] - s.red[0]);
        s.mq[tid] = __expf(s.mq[tid] - s.red[1]);
    }
    __syncthreads();
    if (wid == 0) {
        float v = 0.f;
        for (int t = lane; t < TT; t += 32) v += s.mc[t];
        v = warp_sum(v);
        if (lane == 0) s.red[2] = 1.f / v;
    }
    if (wid == 1) {
        float v = 0.f;
        for (int t = lane; t < TT; t += 32) v += s.mq[t];
        v = warp_sum(v);
        if (lane == 0) s.red[3] = 1.f / v;
    }
    __syncthreads();
    if (tid < TT) {
        g_mult[(b * 2 + 0) * TT + tid] = 1.f + s.mc[tid] * s.red[2];
        g_mult[(b * 2 + 1) * TT + tid] = 1.f + s.mq[tid] * s.red[3];
    }
}

// ============================ Kernel B =====================================
#define BTPB 256
#define NSL 4
#define SLCH (CC / NSL)   // 160

__global__ void __launch_bounds__(BTPB)
apply_kernel(const float* __restrict__ cls_all, const float* __restrict__ qry_all,
             float* __restrict__ oc_all, float* __restrict__ oq_all) {
    __shared__ float mult[TT];
    const int b    = blockIdx.y;
    const int sx   = blockIdx.x;
    const int side = sx >= NSL;
    const int sl   = side ? sx - NSL : sx;
    const int tid  = threadIdx.x;

    if (tid < TT) mult[tid] = g_mult[(b * 2 + side) * TT + tid];
    __syncthreads();

    const size_t off = (size_t)b * CC * TT + (size_t)sl * SLCH * TT;
    const float4* in4 = reinterpret_cast<const float4*>((side ? qry_all : cls_all) + off);
    float4* out4 = reinterpret_cast<float4*>((side ? oq_all : oc_all) + off);
    const float4* m4 = reinterpret_cast<const float4*>(mult);
    const int N4 = SLCH * TT / 4;
#pragma unroll 4
    for (int i = tid; i < N4; i += BTPB) {
        float4 v = in4[i];
        float4 a = m4[i % 49];
        v.x *= a.x; v.y *= a.y; v.z *= a.z; v.w *= a.w;
        out4[i] = v;
    }
}

extern "C" void kernel_launch(void* const* d_in, const int* in_sizes, int n_in,
                              void* d_out, int out_size) {
    const float* cls = (const float*)d_in[0];
    const float* qry = (const float*)d_in[1];
    const float* cw1 = (const float*)d_in[2];
    const float* cb1 = (const float*)d_in[3];
    const float* cw2 = (const float*)d_in[4];
    const float* cb2 = (const float*)d_in[5];
    const float* qw1 = (const float*)d_in[6];
    const float* qb1 = (const float*)d_in[7];
    const float* qw2 = (const float*)d_in[8];
    const float* qb2 = (const float*)d_in[9];

    const int B = in_sizes[0] / (CC * TT);  // 512
    float* oc = (float*)d_out;
    float* oq = oc + (size_t)B * CC * TT;

    cudaFuncSetAttribute(corr_mma_kernel,
                         cudaFuncAttributeMaxDynamicSharedMemorySize, DYN_SMEM);
    corr_mma_kernel<<<B, TPB, DYN_SMEM>>>(cls, qry,
                                          cw1, cb1, cw2, cb2,
                                          qw1, qb1, qw2, qb2);

    dim3 bgrid(2 * NSL, B, 1);
    apply_kernel<<<bgrid, BTPB>>>(cls, qry, oc, oq);
}

// round 16
// speedup vs baseline: 1.9327x; 1.9327x over previous
#include <cuda_runtime.h>
#include <cuda_bf16.h>
#include <cooperative_groups.h>
#include <math.h>

namespace cg = cooperative_groups;

#define TT 196            // tokens
#define TQ 49             // token quads
#define CC 640            // channels
#define CLN 10            // cluster: 5 channel-chunks x 2 tensors
#define GRP 5             // chunks per tensor
#define CHUNK 128         // channels per CTA
#define TPB 256
#define NW 8
#define TILE_ELEMS (CHUNK * TT)             // 25088
#define TILE_BYTES (TILE_ELEMS * 2)         // 50176 (bf16)

__device__ __forceinline__ float warp_sum(float v) {
#pragma unroll
    for (int o = 16; o; o >>= 1) v += __shfl_xor_sync(0xffffffffu, v, o);
    return v;
}
__device__ __forceinline__ float warp_max(float v) {
#pragma unroll
    for (int o = 16; o; o >>= 1) v = fmaxf(v, __shfl_xor_sync(0xffffffffu, v, o));
    return v;
}
__device__ __forceinline__ void cluster_arrive_() {
    asm volatile("barrier.cluster.arrive.aligned;" ::: "memory");
}
__device__ __forceinline__ void cluster_wait_() {
    asm volatile("barrier.cluster.wait.aligned;" ::: "memory");
}

struct StateA {
    alignas(16) float part[TT];   // column-pass partial (remote-read by group)
    alignas(16) float invn[TT];   // 1/||token||
    alignas(16) float m[TT];      // m, then logits
    alignas(16) float kw[TT];     // k*invn, then 1+attn (float4-readable)
    float bar[CHUNK];             // my bar chunk (remote-read by peer)
    float v[CHUNK];               // my v chunk   (remote-read by peer)
    float obar[CHUNK];            // local copy of peer bar / v
    float h[32];                  // MLP hidden
    float red[2];                 // softmax reduce
};

__global__ void __launch_bounds__(TPB, 4)
fused_attn_kernel(const float* __restrict__ cls_all, const float* __restrict__ qry_all,
                  const float* __restrict__ cw1, const float* __restrict__ cb1,
                  const float* __restrict__ cw2, const float* __restrict__ cb2,
                  const float* __restrict__ qw1, const float* __restrict__ qb1,
                  const float* __restrict__ qw2, const float* __restrict__ qb2,
                  float* __restrict__ oc_all, float* __restrict__ oq_all) {
    extern __shared__ __nv_bfloat16 tile[];   // [CHUNK][TT] bf16
    __shared__ StateA s;

    cg::cluster_group cl = cg::this_cluster();
    const int tid  = threadIdx.x;
    const int lane = tid & 31;
    const int wid  = tid >> 5;
    const unsigned rank  = cl.block_rank();           // 0..9
    const bool isClass   = rank < GRP;
    const unsigned chunk = isClass ? rank : rank - GRP;
    const unsigned gbase = isClass ? 0u : (unsigned)GRP;
    const unsigned peer  = isClass ? rank + GRP : rank - GRP;
    const int batch = blockIdx.x / CLN;

    const size_t off = (size_t)batch * CC * TT + (size_t)chunk * CHUNK * TT;
    const float* X = (isClass ? cls_all : qry_all) + off;
    float*       O = (isClass ? oc_all  : oq_all ) + off;

    // Class CTAs run the QUERY-side MLP (their m partial is m_q) and their
    // v-pass produces v_q for the peer; symmetric for query CTAs.
    const float* w1 = isClass ? qw1 : cw1;
    const float* b1 = isClass ? qb1 : cb1;
    const float* w2 = isClass ? qw2 : cw2;
    const float* b2 = isClass ? qb2 : cb2;

    // ---- load: global fp32 -> bf16 tile ------------------------------------
    {
        const float4* g4 = reinterpret_cast<const float4*>(X);
        uint4* t16 = reinterpret_cast<uint4*>(tile);
        const int NU = TILE_ELEMS / 8;  // 3136 uint4 (8 bf16 each)
        for (int i = tid; i < NU; i += TPB) {
            float4 a = g4[2 * i];
            float4 b = g4[2 * i + 1];
            __nv_bfloat162 p0 = __floats2bfloat162_rn(a.x, a.y);
            __nv_bfloat162 p1 = __floats2bfloat162_rn(a.z, a.w);
            __nv_bfloat162 p2 = __floats2bfloat162_rn(b.x, b.y);
            __nv_bfloat162 p3 = __floats2bfloat162_rn(b.z, b.w);
            uint4 u;
            u.x = *reinterpret_cast<unsigned*>(&p0);
            u.y = *reinterpret_cast<unsigned*>(&p1);
            u.z = *reinterpret_cast<unsigned*>(&p2);
            u.w = *reinterpret_cast<unsigned*>(&p3);
            t16[i] = u;
        }
    }
    __syncthreads();

    // ---- Phase 1: sumsq partial over my channels ---------------------------
    if (tid < TT) {
        float acc = 0.f;
#pragma unroll 8
        for (int c = 0; c < CHUNK; ++c) {
            float v = __bfloat162float(tile[c * TT + tid]);
            acc = fmaf(v, v, acc);
        }
        s.part[tid] = acc;
    }
    cl.sync();  // S1

    // ---- invn (group reduce) + bar (local row reduce) ----------------------
    if (tid < TT) {
        float ss = 0.f;
#pragma unroll
        for (unsigned i = 0; i < GRP; ++i)
            ss += cl.map_shared_rank(s.part, gbase + i)[tid];
        s.invn[tid] = 1.f / fmaxf(sqrtf(ss), 1e-12f);
    }
    __syncthreads();
    for (int c = wid; c < CHUNK; c += NW) {
        const __nv_bfloat162* row = reinterpret_cast<const __nv_bfloat162*>(tile + c * TT);
        float acc = 0.f;
        for (int i = lane; i < TT / 2; i += 32) {
            float2 x = __bfloat1622float2(row[i]);
            acc = fmaf(x.x, s.invn[2 * i], acc);
            acc = fmaf(x.y, s.invn[2 * i + 1], acc);
        }
        acc = warp_sum(acc);
        if (lane == 0) s.bar[c] = acc * (1.f / (float)TT);
    }
    cl.sync();  // S2

    // ---- m partial: sum_c peer_bar[c] * tile[c][t] -------------------------
    if (tid < CHUNK) s.obar[tid] = cl.map_shared_rank(s.bar, peer)[tid];
    __syncthreads();
    if (tid < TT) {
        float acc = 0.f;
#pragma unroll 8
        for (int c = 0; c < CHUNK; ++c)
            acc = fmaf(s.obar[c], __bfloat162float(tile[c * TT + tid]), acc);
        s.part[tid] = acc;
    }
    cl.sync();  // S3

    // ---- m reduce, MLP -> kw, v row pass -----------------------------------
    if (tid < TT) {
        float mm = 0.f;
#pragma unroll
        for (unsigned i = 0; i < GRP; ++i)
            mm += cl.map_shared_rank(s.part, gbase + i)[tid];
        s.m[tid] = mm * s.invn[tid];
    }
    __syncthreads();
    {   // hidden: 256 thr = 32 units x 8 split-K
        const int hh = tid >> 3;
        const int tg = tid & 7;
        float acc = 0.f;
        for (int t = tg; t < TT; t += 8)
            acc = fmaf(s.m[t], w1[t * 32 + hh], acc);
#pragma unroll
        for (int o = 4; o; o >>= 1) acc += __shfl_xor_sync(0xffffffffu, acc, o);
        if (tg == 0) s.h[hh] = fmaxf(acc + b1[hh], 0.f);
    }
    __syncthreads();
    if (tid < TT) {
        float acc = b2[tid];
#pragma unroll
        for (int hh = 0; hh < 32; ++hh)
            acc = fmaf(s.h[hh], w2[hh * TT + tid], acc);
        s.kw[tid] = acc * s.invn[tid];
    }
    __syncthreads();
    for (int c = wid; c < CHUNK; c += NW) {
        const __nv_bfloat162* row = reinterpret_cast<const __nv_bfloat162*>(tile + c * TT);
        float acc = 0.f;
        for (int i = lane; i < TT / 2; i += 32) {
            float2 x = __bfloat1622float2(row[i]);
            acc = fmaf(x.x, s.kw[2 * i], acc);
            acc = fmaf(x.y, s.kw[2 * i + 1], acc);
        }
        acc = warp_sum(acc);
        if (lane == 0) s.v[c] = acc;
    }
    cl.sync();  // S4

    // ---- logit partial: sum_c peer_v[c] * tile[c][t] -----------------------
    if (tid < CHUNK) s.obar[tid] = cl.map_shared_rank(s.v, peer)[tid];
    __syncthreads();
    if (tid < TT) {
        float acc = 0.f;
#pragma unroll 8
        for (int c = 0; c < CHUNK; ++c)
            acc = fmaf(s.obar[c], __bfloat162float(tile[c * TT + tid]), acc);
        s.part[tid] = acc;
    }
    cl.sync();  // S5

    // ---- logits reduce (last remote reads), softmax ------------------------
    if (tid < TT) {
        float ll = 0.f;
#pragma unroll
        for (unsigned i = 0; i < GRP; ++i)
            ll += cl.map_shared_rank(s.part, gbase + i)[tid];
        s.m[tid] = ll * s.invn[tid] * 40.f;   // /0.025
    }
    __syncthreads();
    cluster_arrive_();   // past all my remote reads; wait at kernel end

    if (wid == 0) {
        float v = -3.4e38f;
        for (int t = lane; t < TT; t += 32) v = fmaxf(v, s.m[t]);
        v = warp_max(v);
        if (lane == 0) s.red[0] = v;
    }
    __syncthreads();
    if (tid < TT) s.m[tid] = __expf(s.m[tid] - s.red[0]);
    __syncthreads();
    if (wid == 0) {
        float v = 0.f;
        for (int t = lane; t < TT; t += 32) v += s.m[t];
        v = warp_sum(v);
        if (lane == 0) s.red[1] = 1.f / v;
    }
    __syncthreads();
    if (tid < TT) s.kw[tid] = 1.f + s.m[tid] * s.red[1];   // multiplier
    __syncthreads();

    // ---- fused epilogue: stream fp32 chunk from GMEM, scale, write ---------
    {
        const float4* in4 = reinterpret_cast<const float4*>(X);
        float4* out4 = reinterpret_cast<float4*>(O);
        const float4* m4 = reinterpret_cast<const float4*>(s.kw);
        const int N4 = TILE_ELEMS / 4;   // 6272; channel row = 49 quads
#pragma unroll 4
        for (int i = tid; i < N4; i += TPB) {
            float4 v = in4[i];
            float4 a = m4[i % TQ];
            v.x *= a.x; v.y *= a.y; v.z *= a.z; v.w *= a.w;
            out4[i] = v;
        }
    }

    cluster_wait_();  // keep SMEM alive until peers finished remote reads
}

extern "C" void kernel_launch(void* const* d_in, const int* in_sizes, int n_in,
                              void* d_out, int out_size) {
    const float* cls = (const float*)d_in[0];
    const float* qry = (const float*)d_in[1];
    const float* cw1 = (const float*)d_in[2];
    const float* cb1 = (const float*)d_in[3];
    const float* cw2 = (const float*)d_in[4];
    const float* cb2 = (const float*)d_in[5];
    const float* qw1 = (const float*)d_in[6];
    const float* qb1 = (const float*)d_in[7];
    const float* qw2 = (const float*)d_in[8];
    const float* qb2 = (const float*)d_in[9];

    const int B = in_sizes[0] / (CC * TT);  // 512
    float* oc = (float*)d_out;
    float* oq = oc + (size_t)B * CC * TT;

    cudaFuncSetAttribute(fused_attn_kernel,
                         cudaFuncAttributeMaxDynamicSharedMemorySize, TILE_BYTES);
    cudaFuncSetAttribute(fused_attn_kernel,
                         cudaFuncAttributeNonPortableClusterSizeAllowed, 1);

    cudaLaunchConfig_t cfg = {};
    cfg.gridDim  = dim3(B * CLN, 1, 1);
    cfg.blockDim = dim3(TPB, 1, 1);
    cfg.dynamicSmemBytes = TILE_BYTES;
    cudaLaunchAttribute attrs[1];
    attrs[0].id = cudaLaunchAttributeClusterDimension;
    attrs[0].val.clusterDim = {CLN, 1, 1};
    cfg.attrs = attrs;
    cfg.numAttrs = 1;

    cudaLaunchKernelEx(&cfg, fused_attn_kernel,
                       cls, qry, cw1, cb1, cw2, cb2, qw1, qb1, qw2, qb2, oc, oq);
}